// round 16
// baseline (speedup 1.0000x reference)
#include <cuda_runtime.h>
#include <cuda_fp16.h>
#include <stdint.h>

#define BB 2
#define TT 2048
#define CC 1024
#define HH 16
#define DD 64
#define MM (BB*TT)   // 4096

// ---------------------------------------------------------------------------
// Fragment-layout scratch (fp16 pairs packed in u32), global scratch.
// ---------------------------------------------------------------------------
__device__ uint32_t g_xf[32u*16u*4096u];
__device__ uint32_t g_wqf[8u*16u*4608u];
__device__ uint32_t g_wkf[8u*16u*4608u];
__device__ uint32_t g_wvf[8u*16u*4608u];
__device__ uint32_t g_wpf[8u*16u*4608u];
__device__ uint32_t g_qf[32u*32u*2048u];
__device__ uint32_t g_kf[32u*32u*2048u];
__device__ uint32_t g_vf[32u*32u*2048u];
__device__ uint32_t g_af[32u*16u*4096u];

// ---------------------------------------------------------------------------
__device__ __forceinline__ uint32_t f2h2(float a, float b) {
    __half2 h = __floats2half2_rn(a, b);
    return *reinterpret_cast<uint32_t*>(&h);
}
__device__ __forceinline__ uint32_t ex2h2(uint32_t x) {
    uint32_t r; asm("ex2.approx.f16x2 %0, %1;" : "=r"(r) : "r"(x)); return r;
}
__device__ __forceinline__ uint32_t smem_u32(const void* p) {
    uint32_t a;
    asm("{ .reg .u64 t; cvta.to.shared.u64 t, %1; cvt.u32.u64 %0, t; }" : "=r"(a) : "l"(p));
    return a;
}
#define CP16(s, g) asm volatile("cp.async.cg.shared.global [%0], [%1], 16;" :: "r"(s), "l"(g) : "memory")
#define CPC()      asm volatile("cp.async.commit_group;" ::: "memory")
#define CPW(n)     asm volatile("cp.async.wait_group %0;" :: "n"(n) : "memory")

__device__ __forceinline__ void mma16(float* c, const uint32_t* a, const uint32_t* b) {
    asm volatile("mma.sync.aligned.m16n8k16.row.col.f32.f16.f16.f32 "
        "{%0,%1,%2,%3}, {%4,%5,%6,%7}, {%8,%9}, {%0,%1,%2,%3};"
        : "+f"(c[0]), "+f"(c[1]), "+f"(c[2]), "+f"(c[3])
        : "r"(a[0]), "r"(a[1]), "r"(a[2]), "r"(a[3]), "r"(b[0]), "r"(b[1]));
}

// ---- fragment layout bijections (u32 index; p = k-pair index) ----
__device__ __forceinline__ int a_off(int row, int p) {      // gemm A: row 0..127
    int mt = row >> 4, ga = row & 7, hm = (row >> 3) & 1;
    int ks = p >> 3, rem = p & 7, tq = rem & 3, hk = rem >> 2;
    int sl = (tq ^ (ga >> 1) ^ ks) & 3;
    return ks*1024 + mt*128 + ga*16 + sl*4 + hk*2 + hm;
}
__device__ __forceinline__ int b_off(int row, int p) {      // gemm B: row 0..127
    int nt = row >> 3, gb = row & 7;
    int ks = p >> 3, rem = p & 7, tq = rem & 3, hk = rem >> 2;
    int sl = (tq ^ (gb >> 1) ^ (nt & 3) ^ ks) & 3;
    return ks*1152 + nt*72 + gb*8 + sl*2 + hk;
}
__device__ __forceinline__ int qa_off(int r, int p) {       // attn Q A-frag: r 0..63
    int mt = r >> 4, ga = r & 7, hm = (r >> 3) & 1;
    int ks = p >> 3, rem = p & 7, tq = rem & 3, hk = rem >> 2;
    int sl = (tq ^ (ga >> 1) ^ ks) & 3;
    return ks*512 + mt*128 + ga*16 + sl*4 + hk*2 + hm;
}
// attn K paired B-frag (n=tok, k=d): nt pairs share one uint4 slot.
__device__ __forceinline__ int kb2_off(int r, int p) {      // r tok 0..63, p=d>>1
    int ntp = r >> 4, hn = (r >> 3) & 1, gb = r & 7;
    int ks = p >> 3, rem = p & 7, tq = rem & 3, hk = rem >> 2;
    int sl = (tq ^ (gb >> 1) ^ ks) & 3;
    return ks*512 + ntp*128 + gb*16 + sl*4 + hn*2 + hk;
}
// attn V paired B-frag (n=d, k=tok): dt pairs share one uint4 slot.
__device__ __forceinline__ int vb2_off_u32(int tok, int d) {
    int dtp = d >> 4, hd = (d >> 3) & 1, gv = d & 7;
    int p = tok >> 1;
    int ks = p >> 3, rem = p & 7, tq = rem & 3, hk = rem >> 2;
    int sl = (tq ^ (gv >> 1) ^ ks) & 3;
    return ks*512 + dtp*128 + gv*16 + sl*4 + hd*2 + hk;     // half sel = tok&1
}

// ---------------------------------------------------------------------------
// Merged prep: grid (1024, 8). y in 0..3 -> weight matrix y; y in 4..7 ->
// quarter (y-4) of X.
// ---------------------------------------------------------------------------
__global__ __launch_bounds__(256) void prep_all(
    const float* __restrict__ X,
    const float* __restrict__ W0, const float* __restrict__ W1,
    const float* __restrict__ W2, const float* __restrict__ W3,
    uint32_t* __restrict__ XO,
    uint32_t* __restrict__ O0, uint32_t* __restrict__ O1,
    uint32_t* __restrict__ O2, uint32_t* __restrict__ O3)
{
    int y = blockIdx.y;
    if (y < 4) {
        const float* W; uint32_t* out;
        switch (y) {
            case 0: W = W0; out = O0; break;
            case 1: W = W1; out = O1; break;
            case 2: W = W2; out = O2; break;
            default: W = W3; out = O3; break;
        }
        int idx = blockIdx.x * 256 + threadIdx.x;
        int n = idx >> 8, kq = idx & 255;
        float4 v = *(const float4*)(W + (size_t)n * CC + kq * 4);
        int row = n & 127, nblk = n >> 7;
        int kblk = kq >> 4, p0 = (kq & 15) * 2;
        uint32_t* base = out + ((size_t)nblk * 16 + kblk) * 4608;
        base[b_off(row, p0)]     = f2h2(v.x, v.y);
        base[b_off(row, p0 + 1)] = f2h2(v.z, v.w);
    } else {
        int idx = ((y - 4) * 1024 + blockIdx.x) * 256 + threadIdx.x;
        int m = idx >> 8, kq = idx & 255;
        float4 v = *(const float4*)(X + (size_t)m * CC + kq * 4);
        int row = m & 127, mblk = m >> 7;
        int kblk = kq >> 4, p0 = (kq & 15) * 2;
        uint32_t* base = XO + ((size_t)mblk * 16 + kblk) * 4096;
        base[a_off(row, p0)]     = f2h2(v.x, v.y);
        base[a_off(row, p0 + 1)] = f2h2(v.z, v.w);
    }
}

// ---------------------------------------------------------------------------
// fp16 GEMM. __launch_bounds__(256,2): 2 CTAs/SM.
// ---------------------------------------------------------------------------
#define GST 3
#define QSCALE_LOG2E 0.18033688011112042f   // 0.125 * log2(e)

__device__ __forceinline__ void gemm_body(
    const uint32_t* __restrict__ Af, const uint32_t* __restrict__ Bf,
    const float* __restrict__ bias, float* __restrict__ outl,
    uint32_t* __restrict__ outf, int mode, float scale,
    uint32_t* sm, int mblk, int nblk)
{
    const uint32_t sb = smem_u32(sm);
    const int tid = threadIdx.x, warp = tid >> 5, lane = tid & 31;
    const int g = lane >> 2, t = lane & 3;
    const int wm = warp >> 2, wn = warp & 3;

    const uint32_t* srcA0 = Af + (size_t)mblk * 16 * 4096;
    const uint32_t* srcB0 = Bf + (size_t)nblk * 16 * 4608;

    auto issue = [&](int kb, int st) {
        uint32_t dA = sb + st * 8704 * 4;
        uint32_t dB = dA + 4096 * 4;
        const uint32_t* sA = srcA0 + kb * 4096;
        const uint32_t* sB = srcB0 + kb * 4608;
        #pragma unroll
        for (int i = 0; i < 4; i++) { int c = tid + 256 * i; CP16(dA + c*16, sA + c*4); }
        #pragma unroll
        for (int i = 0; i < 4; i++) { int c = tid + 256 * i; CP16(dB + c*16, sB + c*4); }
        if (tid < 128) { int c = 1024 + tid; CP16(dB + c*16, sB + c*4); }
    };

    issue(0, 0); CPC();
    issue(1, 1); CPC();

    float acc[4][4][4] = {};

    for (int kb = 0; kb < 16; kb++) {
        if (kb + GST - 1 < 16) issue(kb + GST - 1, (kb + GST - 1) % GST);
        CPC();
        CPW(2);
        __syncthreads();
        const uint32_t* As = sm + (kb % GST) * 8704;
        const uint32_t* Bs = As + 4096;
        #pragma unroll
        for (int ks = 0; ks < 4; ks++) {
            uint32_t a[4][4], b[4][2];
            #pragma unroll
            for (int mt = 0; mt < 4; mt++) {
                int mtile = wm * 4 + mt;
                int slot = (t ^ (g >> 1) ^ ks) & 3;
                uint4 v = *(const uint4*)&As[ks*1024 + mtile*128 + g*16 + slot*4];
                a[mt][0] = v.x; a[mt][1] = v.y; a[mt][2] = v.z; a[mt][3] = v.w;
            }
            #pragma unroll
            for (int nt = 0; nt < 4; nt++) {
                int ntile = wn * 4 + nt;
                int slot = (t ^ (g >> 1) ^ (ntile & 3) ^ ks) & 3;
                uint2 v = *(const uint2*)&Bs[ks*1152 + ntile*72 + g*8 + slot*2];
                b[nt][0] = v.x; b[nt][1] = v.y;
            }
            #pragma unroll
            for (int mt = 0; mt < 4; mt++)
                #pragma unroll
                for (int nt = 0; nt < 4; nt++)
                    mma16(acc[mt][nt], a[mt], b[nt]);
        }
        __syncthreads();
    }

    // ---- epilogue ----
    const int m0 = mblk * 128, n0 = nblk * 128;
    #pragma unroll
    for (int mt = 0; mt < 4; mt++) {
        #pragma unroll
        for (int nt = 0; nt < 4; nt++) {
            int n = n0 + wn * 32 + nt * 8 + 2 * t;
            float b0 = bias[n], b1 = bias[n + 1];
            #pragma unroll
            for (int hm = 0; hm < 2; hm++) {
                int m = m0 + wm * 64 + mt * 16 + g + hm * 8;
                float v0 = (acc[mt][nt][2*hm + 0] + b0) * scale;
                float v1 = (acc[mt][nt][2*hm + 1] + b1) * scale;
                int b_ = m >> 11, t_ = m & 2047;
                int h_ = n >> 6, d_ = n & 63;
                int bh = b_ * HH + h_, tile = t_ >> 6, r = t_ & 63;
                if (mode == 0) {
                    uint32_t* fb = outf + ((size_t)bh * 32 + tile) * 2048;
                    fb[qa_off(r, d_ >> 1)] = f2h2(v0, v1);
                } else if (mode == 3) {
                    *(float2*)&outl[(size_t)m * CC + n] = make_float2(v0, v1);
                } else {
                    *(float2*)&outl[(((size_t)bh * TT) + t_) * DD + d_] = make_float2(v0, v1);
                    uint32_t* fb = outf + ((size_t)bh * 32 + tile) * 2048;
                    if (mode == 1) {
                        fb[kb2_off(r, d_ >> 1)] = f2h2(v0, v1);
                    } else {
                        __half* hb = (__half*)fb;
                        hb[vb2_off_u32(r, d_    ) * 2 + (r & 1)] = __float2half_rn(v0);
                        hb[vb2_off_u32(r, d_ + 1) * 2 + (r & 1)] = __float2half_rn(v1);
                    }
                }
            }
        }
    }
}

__global__ void __launch_bounds__(256, 2) gemm_qkv(
    const uint32_t* __restrict__ Af,
    const uint32_t* __restrict__ Bq, const uint32_t* __restrict__ Bk, const uint32_t* __restrict__ Bv,
    const float* __restrict__ bq, const float* __restrict__ bk, const float* __restrict__ bv,
    float* __restrict__ kout, float* __restrict__ vout,
    uint32_t* __restrict__ qf, uint32_t* __restrict__ kfr, uint32_t* __restrict__ vfr)
{
    extern __shared__ __align__(16) uint32_t sm[];
    const int z = blockIdx.z;
    const uint32_t* Bf = (z == 0) ? Bq : (z == 1) ? Bk : Bv;
    const float* bias   = (z == 0) ? bq : (z == 1) ? bk : bv;
    float* outl         = (z == 1) ? kout : (z == 2) ? vout : nullptr;
    uint32_t* outf      = (z == 0) ? qf : (z == 1) ? kfr : vfr;
    float scale         = (z == 0) ? QSCALE_LOG2E : 1.0f;
    gemm_body(Af, Bf, bias, outl, outf, z, scale, sm, blockIdx.x, blockIdx.y);
}

__global__ void __launch_bounds__(256, 2) gemm_proj(
    const uint32_t* __restrict__ Af, const uint32_t* __restrict__ Bf,
    const float* __restrict__ bias, float* __restrict__ outl)
{
    extern __shared__ __align__(16) uint32_t sm[];
    gemm_body(Af, Bf, bias, outl, nullptr, 3, 1.0f, sm, blockIdx.x, blockIdx.y);
}

// ---------------------------------------------------------------------------
// fp16 flash attention v9:
//  - 3-stage KV ring but Q is loaded INTO stage 2's area (Q only needed until
//    the register hoist; first write to stage 2 = kv(2), issued after hoist).
//    smem = 3 x 4096 u32 = 49152 B -> 4 CTAs/SM restored (was 3 in R15).
//  - Liveness-reduced order: S(A) -> ex2(A) -> S(B) -> PV(A) -> ex2(B) -> PV(B)
//    (s half A dies into aA before s half B materializes).
// ---------------------------------------------------------------------------
__global__ void __launch_bounds__(128, 4) attn_f(
    const uint32_t* __restrict__ qf, const uint32_t* __restrict__ kf,
    const uint32_t* __restrict__ vf, uint32_t* __restrict__ af)
{
    extern __shared__ __align__(16) uint32_t sm[];
    const uint32_t sb = smem_u32(sm);

    const int qt = gridDim.x - 1 - blockIdx.x;      // 0..31, longest-first
    const int bh = blockIdx.y;
    const int tid = threadIdx.x, warp = tid >> 5, lane = tid & 31;
    const int g = lane >> 2, t = lane & 3;

    auto issue_kv = [&](int it, int st) {
        uint32_t dK = sb + (uint32_t)st * 4096u * 4u;
        uint32_t dV = dK + 2048 * 4;
        const uint32_t* sK = kf + ((size_t)bh * 32 + it) * 2048;
        const uint32_t* sV = vf + ((size_t)bh * 32 + it) * 2048;
        #pragma unroll
        for (int i = 0; i < 4; i++) { int c = tid + 128 * i; CP16(dK + c*16, sK + c*4); }
        #pragma unroll
        for (int i = 0; i < 4; i++) { int c = tid + 128 * i; CP16(dV + c*16, sV + c*4); }
    };

    {   // prologue: Q into stage-2 area; kv0 -> stage0; kv1 -> stage1.
        const uint32_t* sQ = qf + ((size_t)bh * 32 + qt) * 2048;
        uint32_t dQ = sb + 2u * 4096u * 4u;
        #pragma unroll
        for (int i = 0; i < 4; i++) { int c = tid + 128 * i; CP16(dQ + c*16, sQ + c*4); }
        CPC();
        issue_kv(0, 0); CPC();
        if (qt >= 1) issue_kv(1, 1);
        CPC();
    }
    CPW(2);                 // Q arrived
    __syncthreads();

    // hoist Q fragments from stage-2 area: warp w -> mtile w
    uint32_t aq[4][4];
    #pragma unroll
    for (int ks = 0; ks < 4; ks++) {
        int sl = (t ^ (g >> 1) ^ ks) & 3;
        uint4 av = *(const uint4*)&sm[2*4096 + ks*512 + warp*128 + g*16 + sl*4];
        aq[ks][0] = av.x; aq[ks][1] = av.y; aq[ks][2] = av.z; aq[ks][3] = av.w;
    }
    __syncthreads();        // all warps done reading Q before stage 2 reuse

    float o[8][4] = {};
    float csum[4] = {};
    const uint32_t bones[2] = {0x3C003C00u, 0x3C003C00u};   // ones fp16x2

    for (int it = 0; it <= qt; it++) {
        CPW(1);             // kv(it) ready; kv(it+1) may remain in flight
        __syncthreads();
        if (it + 2 <= qt) issue_kv(it + 2, (it + 2) % 3);
        CPC();
        const uint32_t* Kf = sm + (it % 3) * 4096;
        const uint32_t* Vf = Kf + 2048;

        // ---- S half A: n-tiles 0..3 ----
        float sA[4][4] = {};
        #pragma unroll
        for (int ks = 0; ks < 4; ks++) {
            int sl = (t ^ (g >> 1) ^ ks) & 3;
            #pragma unroll
            for (int ntp = 0; ntp < 2; ntp++) {
                uint4 kv4 = *(const uint4*)&Kf[ks*512 + ntp*128 + g*16 + sl*4];
                uint32_t blo[2] = {kv4.x, kv4.y};
                uint32_t bhi[2] = {kv4.z, kv4.w};
                mma16(sA[2*ntp],     aq[ks], blo);
                mma16(sA[2*ntp + 1], aq[ks], bhi);
            }
        }
        // ---- ex2(A): sA dies into aA ----
        uint32_t aA[2][4];
        #pragma unroll
        for (int kp = 0; kp < 2; kp++) {
            aA[kp][0] = ex2h2(f2h2(sA[2*kp][0],   sA[2*kp][1]));
            aA[kp][1] = ex2h2(f2h2(sA[2*kp][2],   sA[2*kp][3]));
            aA[kp][2] = ex2h2(f2h2(sA[2*kp+1][0], sA[2*kp+1][1]));
            aA[kp][3] = ex2h2(f2h2(sA[2*kp+1][2], sA[2*kp+1][3]));
        }
        // ---- S half B: n-tiles 4..7 ----
        float sB[4][4] = {};
        #pragma unroll
        for (int ks = 0; ks < 4; ks++) {
            int sl = (t ^ (g >> 1) ^ ks) & 3;
            #pragma unroll
            for (int ntp = 2; ntp < 4; ntp++) {
                uint4 kv4 = *(const uint4*)&Kf[ks*512 + ntp*128 + g*16 + sl*4];
                uint32_t blo[2] = {kv4.x, kv4.y};
                uint32_t bhi[2] = {kv4.z, kv4.w};
                mma16(sB[2*(ntp-2)],     aq[ks], blo);
                mma16(sB[2*(ntp-2) + 1], aq[ks], bhi);
            }
        }
        // ---- PV half A (overlaps: nothing depends on it until epilogue) ----
        #pragma unroll
        for (int kp = 0; kp < 2; kp++) {
            mma16(csum, aA[kp], bones);
            int sl = (t ^ (g >> 1) ^ kp) & 3;
            #pragma unroll
            for (int dtp = 0; dtp < 4; dtp++) {
                uint4 v4 = *(const uint4*)&Vf[kp*512 + dtp*128 + g*16 + sl*4];
                uint32_t blo[2] = {v4.x, v4.y};
                uint32_t bhi[2] = {v4.z, v4.w};
                mma16(o[2*dtp],     aA[kp], blo);
                mma16(o[2*dtp + 1], aA[kp], bhi);
            }
        }
        // ---- ex2(B): sB dies into aB (MUFU overlaps PV(A) tensor work) ----
        uint32_t aB[2][4];
        #pragma unroll
        for (int kp = 0; kp < 2; kp++) {
            aB[kp][0] = ex2h2(f2h2(sB[2*kp][0],   sB[2*kp][1]));
            aB[kp][1] = ex2h2(f2h2(sB[2*kp][2],   sB[2*kp][3]));
            aB[kp][2] = ex2h2(f2h2(sB[2*kp+1][0], sB[2*kp+1][1]));
            aB[kp][3] = ex2h2(f2h2(sB[2*kp+1][2], sB[2*kp+1][3]));
        }
        // ---- PV half B ----
        #pragma unroll
        for (int kp = 0; kp < 2; kp++) {
            int ks = kp + 2;
            mma16(csum, aB[kp], bones);
            int sl = (t ^ (g >> 1) ^ ks) & 3;
            #pragma unroll
            for (int dtp = 0; dtp < 4; dtp++) {
                uint4 v4 = *(const uint4*)&Vf[ks*512 + dtp*128 + g*16 + sl*4];
                uint32_t blo[2] = {v4.x, v4.y};
                uint32_t bhi[2] = {v4.z, v4.w};
                mma16(o[2*dtp],     aB[kp], blo);
                mma16(o[2*dtp + 1], aB[kp], bhi);
            }
        }
    }

    // ---- epilogue: normalize, pack into proj-GEMM A-frag layout ----
    const int b_ = bh >> 4, h_ = bh & 15;
    float inv0 = 1.0f / csum[0];
    float inv1 = 1.0f / csum[2];
    #pragma unroll
    for (int dt = 0; dt < 8; dt++) {
        int pp = 4 * dt + t;                       // head-local pair index
        #pragma unroll
        for (int hm = 0; hm < 2; hm++) {
            int tok = qt * 64 + warp * 16 + g + hm * 8;
            float va = o[dt][2*hm + 0] * (hm ? inv1 : inv0);
            float vb = o[dt][2*hm + 1] * (hm ? inv1 : inv0);
            int m_out = b_ * TT + tok;
            int mb = m_out >> 7, row = m_out & 127;
            af[((size_t)mb * 16 + h_) * 4096 + a_off(row, pp)] = f2h2(va, vb);
        }
    }
}

// ---------------------------------------------------------------------------
extern "C" void kernel_launch(void* const* d_in, const int* in_sizes, int n_in,
                              void* d_out, int out_size)
{
    const float* x  = (const float*)d_in[0];
    const float* Wq = (const float*)d_in[1];
    const float* bq = (const float*)d_in[2];
    const float* Wk = (const float*)d_in[3];
    const float* bk = (const float*)d_in[4];
    const float* Wv = (const float*)d_in[5];
    const float* bv = (const float*)d_in[6];
    const float* Wp = (const float*)d_in[7];
    const float* bp = (const float*)d_in[8];

    float* yout = (float*)d_out;
    float* kout = yout + (size_t)BB * TT * CC;
    float* vout = kout + (size_t)BB * HH * TT * DD;

    uint32_t *xf, *wqf, *wkf, *wvf, *wpf, *qf, *kfr, *vfr, *afr;
    cudaGetSymbolAddress((void**)&xf,  g_xf);
    cudaGetSymbolAddress((void**)&wqf, g_wqf);
    cudaGetSymbolAddress((void**)&wkf, g_wkf);
    cudaGetSymbolAddress((void**)&wvf, g_wvf);
    cudaGetSymbolAddress((void**)&wpf, g_wpf);
    cudaGetSymbolAddress((void**)&qf,  g_qf);
    cudaGetSymbolAddress((void**)&kfr, g_kf);
    cudaGetSymbolAddress((void**)&vfr, g_vf);
    cudaGetSymbolAddress((void**)&afr, g_af);

    const int gsmem = GST * 8704 * 4;          // 104448 B
    const int asmem = 3 * 4096 * 4;            // 49152 B -> 4 CTAs/SM
    cudaFuncSetAttribute(gemm_qkv,  cudaFuncAttributeMaxDynamicSharedMemorySize, gsmem);
    cudaFuncSetAttribute(gemm_proj, cudaFuncAttributeMaxDynamicSharedMemorySize, gsmem);
    cudaFuncSetAttribute(attn_f,    cudaFuncAttributeMaxDynamicSharedMemorySize, asmem);

    prep_all<<<dim3(1024, 8), 256>>>(x, Wq, Wk, Wv, Wp, xf, wqf, wkf, wvf, wpf);

    gemm_qkv<<<dim3(MM / 128, CC / 128, 3), 256, gsmem>>>(
        xf, wqf, wkf, wvf, bq, bk, bv, kout, vout, qf, kfr, vfr);

    attn_f<<<dim3(TT / 64, BB * HH), 128, asmem>>>(qf, kfr, vfr, afr);

    gemm_proj<<<dim3(MM / 128, CC / 128), 256, gsmem>>>(afr, wpf, bp, yout);
}

// round 17
// speedup vs baseline: 1.0221x; 1.0221x over previous
#include <cuda_runtime.h>
#include <cuda_fp16.h>
#include <stdint.h>

#define BB 2
#define TT 2048
#define CC 1024
#define HH 16
#define DD 64
#define MM (BB*TT)   // 4096

// ---------------------------------------------------------------------------
// Fragment-layout scratch (fp16 pairs packed in u32), global scratch.
// ---------------------------------------------------------------------------
__device__ uint32_t g_xf[32u*16u*4096u];
__device__ uint32_t g_wqf[8u*16u*4608u];
__device__ uint32_t g_wkf[8u*16u*4608u];
__device__ uint32_t g_wvf[8u*16u*4608u];
__device__ uint32_t g_wpf[8u*16u*4608u];
__device__ uint32_t g_qf[32u*32u*2048u];
__device__ uint32_t g_kf[32u*32u*2048u];
__device__ uint32_t g_vf[32u*32u*2048u];
__device__ uint32_t g_af[32u*16u*4096u];

// ---------------------------------------------------------------------------
__device__ __forceinline__ uint32_t f2h2(float a, float b) {
    __half2 h = __floats2half2_rn(a, b);
    return *reinterpret_cast<uint32_t*>(&h);
}
__device__ __forceinline__ uint32_t ex2h2(uint32_t x) {
    uint32_t r; asm("ex2.approx.f16x2 %0, %1;" : "=r"(r) : "r"(x)); return r;
}
__device__ __forceinline__ uint32_t smem_u32(const void* p) {
    uint32_t a;
    asm("{ .reg .u64 t; cvta.to.shared.u64 t, %1; cvt.u32.u64 %0, t; }" : "=r"(a) : "l"(p));
    return a;
}
#define CP16(s, g) asm volatile("cp.async.cg.shared.global [%0], [%1], 16;" :: "r"(s), "l"(g) : "memory")
#define CPC()      asm volatile("cp.async.commit_group;" ::: "memory")
#define CPW(n)     asm volatile("cp.async.wait_group %0;" :: "n"(n) : "memory")

__device__ __forceinline__ void mma16(float* c, const uint32_t* a, const uint32_t* b) {
    asm volatile("mma.sync.aligned.m16n8k16.row.col.f32.f16.f16.f32 "
        "{%0,%1,%2,%3}, {%4,%5,%6,%7}, {%8,%9}, {%0,%1,%2,%3};"
        : "+f"(c[0]), "+f"(c[1]), "+f"(c[2]), "+f"(c[3])
        : "r"(a[0]), "r"(a[1]), "r"(a[2]), "r"(a[3]), "r"(b[0]), "r"(b[1]));
}

// ---- fragment layout bijections (u32 index; p = k-pair index) ----
__device__ __forceinline__ int a_off(int row, int p) {      // gemm A: row 0..127
    int mt = row >> 4, ga = row & 7, hm = (row >> 3) & 1;
    int ks = p >> 3, rem = p & 7, tq = rem & 3, hk = rem >> 2;
    int sl = (tq ^ (ga >> 1) ^ ks) & 3;
    return ks*1024 + mt*128 + ga*16 + sl*4 + hk*2 + hm;
}
__device__ __forceinline__ int b_off(int row, int p) {      // gemm B: row 0..127
    int nt = row >> 3, gb = row & 7;
    int ks = p >> 3, rem = p & 7, tq = rem & 3, hk = rem >> 2;
    int sl = (tq ^ (gb >> 1) ^ (nt & 3) ^ ks) & 3;
    return ks*1152 + nt*72 + gb*8 + sl*2 + hk;
}
__device__ __forceinline__ int qa_off(int r, int p) {       // attn Q A-frag: r 0..63
    int mt = r >> 4, ga = r & 7, hm = (r >> 3) & 1;
    int ks = p >> 3, rem = p & 7, tq = rem & 3, hk = rem >> 2;
    int sl = (tq ^ (ga >> 1) ^ ks) & 3;
    return ks*512 + mt*128 + ga*16 + sl*4 + hk*2 + hm;
}
// attn K paired B-frag (n=tok, k=d): nt pairs share one uint4 slot.
__device__ __forceinline__ int kb2_off(int r, int p) {      // r tok 0..63, p=d>>1
    int ntp = r >> 4, hn = (r >> 3) & 1, gb = r & 7;
    int ks = p >> 3, rem = p & 7, tq = rem & 3, hk = rem >> 2;
    int sl = (tq ^ (gb >> 1) ^ ks) & 3;
    return ks*512 + ntp*128 + gb*16 + sl*4 + hn*2 + hk;
}
// attn V paired B-frag (n=d, k=tok): dt pairs share one uint4 slot.
__device__ __forceinline__ int vb2_off_u32(int tok, int d) {
    int dtp = d >> 4, hd = (d >> 3) & 1, gv = d & 7;
    int p = tok >> 1;
    int ks = p >> 3, rem = p & 7, tq = rem & 3, hk = rem >> 2;
    int sl = (tq ^ (gv >> 1) ^ ks) & 3;
    return ks*512 + dtp*128 + gv*16 + sl*4 + hd*2 + hk;     // half sel = tok&1
}

// ---------------------------------------------------------------------------
// Merged prep: grid (1024, 8). y in 0..3 -> weight matrix y; y in 4..7 ->
// quarter (y-4) of X.
// ---------------------------------------------------------------------------
__global__ __launch_bounds__(256) void prep_all(
    const float* __restrict__ X,
    const float* __restrict__ W0, const float* __restrict__ W1,
    const float* __restrict__ W2, const float* __restrict__ W3,
    uint32_t* __restrict__ XO,
    uint32_t* __restrict__ O0, uint32_t* __restrict__ O1,
    uint32_t* __restrict__ O2, uint32_t* __restrict__ O3)
{
    int y = blockIdx.y;
    if (y < 4) {
        const float* W; uint32_t* out;
        switch (y) {
            case 0: W = W0; out = O0; break;
            case 1: W = W1; out = O1; break;
            case 2: W = W2; out = O2; break;
            default: W = W3; out = O3; break;
        }
        int idx = blockIdx.x * 256 + threadIdx.x;
        int n = idx >> 8, kq = idx & 255;
        float4 v = *(const float4*)(W + (size_t)n * CC + kq * 4);
        int row = n & 127, nblk = n >> 7;
        int kblk = kq >> 4, p0 = (kq & 15) * 2;
        uint32_t* base = out + ((size_t)nblk * 16 + kblk) * 4608;
        base[b_off(row, p0)]     = f2h2(v.x, v.y);
        base[b_off(row, p0 + 1)] = f2h2(v.z, v.w);
    } else {
        int idx = ((y - 4) * 1024 + blockIdx.x) * 256 + threadIdx.x;
        int m = idx >> 8, kq = idx & 255;
        float4 v = *(const float4*)(X + (size_t)m * CC + kq * 4);
        int row = m & 127, mblk = m >> 7;
        int kblk = kq >> 4, p0 = (kq & 15) * 2;
        uint32_t* base = XO + ((size_t)mblk * 16 + kblk) * 4096;
        base[a_off(row, p0)]     = f2h2(v.x, v.y);
        base[a_off(row, p0 + 1)] = f2h2(v.z, v.w);
    }
}

// ---------------------------------------------------------------------------
// fp16 GEMM. __launch_bounds__(256,2): 2 CTAs/SM. ONE barrier per kblock:
// CPW(1); sync; issue(kb+2); compute  (prefetch after the barrier covers the
// WAR hazard on the stage being overwritten — same schedule as the attn ring).
// ---------------------------------------------------------------------------
#define GST 3
#define QSCALE_LOG2E 0.18033688011112042f   // 0.125 * log2(e)

__device__ __forceinline__ void gemm_body(
    const uint32_t* __restrict__ Af, const uint32_t* __restrict__ Bf,
    const float* __restrict__ bias, float* __restrict__ outl,
    uint32_t* __restrict__ outf, int mode, float scale,
    uint32_t* sm, int mblk, int nblk)
{
    const uint32_t sb = smem_u32(sm);
    const int tid = threadIdx.x, warp = tid >> 5, lane = tid & 31;
    const int g = lane >> 2, t = lane & 3;
    const int wm = warp >> 2, wn = warp & 3;

    const uint32_t* srcA0 = Af + (size_t)mblk * 16 * 4096;
    const uint32_t* srcB0 = Bf + (size_t)nblk * 16 * 4608;

    auto issue = [&](int kb, int st) {
        uint32_t dA = sb + st * 8704 * 4;
        uint32_t dB = dA + 4096 * 4;
        const uint32_t* sA = srcA0 + kb * 4096;
        const uint32_t* sB = srcB0 + kb * 4608;
        #pragma unroll
        for (int i = 0; i < 4; i++) { int c = tid + 256 * i; CP16(dA + c*16, sA + c*4); }
        #pragma unroll
        for (int i = 0; i < 4; i++) { int c = tid + 256 * i; CP16(dB + c*16, sB + c*4); }
        if (tid < 128) { int c = 1024 + tid; CP16(dB + c*16, sB + c*4); }
    };

    issue(0, 0); CPC();
    issue(1, 1); CPC();

    float acc[4][4][4] = {};

    for (int kb = 0; kb < 16; kb++) {
        CPW(1);                 // kblock kb resident; kb+1 may be in flight
        __syncthreads();        // all warps done reading stage (kb+2)%GST
        if (kb + 2 < 16) issue(kb + 2, (kb + 2) % GST);
        CPC();
        const uint32_t* As = sm + (kb % GST) * 8704;
        const uint32_t* Bs = As + 4096;
        #pragma unroll
        for (int ks = 0; ks < 4; ks++) {
            uint32_t a[4][4], b[4][2];
            #pragma unroll
            for (int mt = 0; mt < 4; mt++) {
                int mtile = wm * 4 + mt;
                int slot = (t ^ (g >> 1) ^ ks) & 3;
                uint4 v = *(const uint4*)&As[ks*1024 + mtile*128 + g*16 + slot*4];
                a[mt][0] = v.x; a[mt][1] = v.y; a[mt][2] = v.z; a[mt][3] = v.w;
            }
            #pragma unroll
            for (int nt = 0; nt < 4; nt++) {
                int ntile = wn * 4 + nt;
                int slot = (t ^ (g >> 1) ^ (ntile & 3) ^ ks) & 3;
                uint2 v = *(const uint2*)&Bs[ks*1152 + ntile*72 + g*8 + slot*2];
                b[nt][0] = v.x; b[nt][1] = v.y;
            }
            #pragma unroll
            for (int mt = 0; mt < 4; mt++)
                #pragma unroll
                for (int nt = 0; nt < 4; nt++)
                    mma16(acc[mt][nt], a[mt], b[nt]);
        }
    }

    // ---- epilogue ----
    const int m0 = mblk * 128, n0 = nblk * 128;
    #pragma unroll
    for (int mt = 0; mt < 4; mt++) {
        #pragma unroll
        for (int nt = 0; nt < 4; nt++) {
            int n = n0 + wn * 32 + nt * 8 + 2 * t;
            float b0 = bias[n], b1 = bias[n + 1];
            #pragma unroll
            for (int hm = 0; hm < 2; hm++) {
                int m = m0 + wm * 64 + mt * 16 + g + hm * 8;
                float v0 = (acc[mt][nt][2*hm + 0] + b0) * scale;
                float v1 = (acc[mt][nt][2*hm + 1] + b1) * scale;
                int b_ = m >> 11, t_ = m & 2047;
                int h_ = n >> 6, d_ = n & 63;
                int bh = b_ * HH + h_, tile = t_ >> 6, r = t_ & 63;
                if (mode == 0) {
                    uint32_t* fb = outf + ((size_t)bh * 32 + tile) * 2048;
                    fb[qa_off(r, d_ >> 1)] = f2h2(v0, v1);
                } else if (mode == 3) {
                    *(float2*)&outl[(size_t)m * CC + n] = make_float2(v0, v1);
                } else {
                    *(float2*)&outl[(((size_t)bh * TT) + t_) * DD + d_] = make_float2(v0, v1);
                    uint32_t* fb = outf + ((size_t)bh * 32 + tile) * 2048;
                    if (mode == 1) {
                        fb[kb2_off(r, d_ >> 1)] = f2h2(v0, v1);
                    } else {
                        __half* hb = (__half*)fb;
                        hb[vb2_off_u32(r, d_    ) * 2 + (r & 1)] = __float2half_rn(v0);
                        hb[vb2_off_u32(r, d_ + 1) * 2 + (r & 1)] = __float2half_rn(v1);
                    }
                }
            }
        }
    }
}

__global__ void __launch_bounds__(256, 2) gemm_qkv(
    const uint32_t* __restrict__ Af,
    const uint32_t* __restrict__ Bq, const uint32_t* __restrict__ Bk, const uint32_t* __restrict__ Bv,
    const float* __restrict__ bq, const float* __restrict__ bk, const float* __restrict__ bv,
    float* __restrict__ kout, float* __restrict__ vout,
    uint32_t* __restrict__ qf, uint32_t* __restrict__ kfr, uint32_t* __restrict__ vfr)
{
    extern __shared__ __align__(16) uint32_t sm[];
    const int z = blockIdx.z;
    const uint32_t* Bf = (z == 0) ? Bq : (z == 1) ? Bk : Bv;
    const float* bias   = (z == 0) ? bq : (z == 1) ? bk : bv;
    float* outl         = (z == 1) ? kout : (z == 2) ? vout : nullptr;
    uint32_t* outf      = (z == 0) ? qf : (z == 1) ? kfr : vfr;
    float scale         = (z == 0) ? QSCALE_LOG2E : 1.0f;
    gemm_body(Af, Bf, bias, outl, outf, z, scale, sm, blockIdx.x, blockIdx.y);
}

__global__ void __launch_bounds__(256, 2) gemm_proj(
    const uint32_t* __restrict__ Af, const uint32_t* __restrict__ Bf,
    const float* __restrict__ bias, float* __restrict__ outl)
{
    extern __shared__ __align__(16) uint32_t sm[];
    gemm_body(Af, Bf, bias, outl, nullptr, 3, 1.0f, sm, blockIdx.x, blockIdx.y);
}

// ---------------------------------------------------------------------------
// fp16 flash attention v8 (exact R15 version — best measured; 3-stage ring,
// prefetch distance 2, separate Q region; smem 57344 B).
// ---------------------------------------------------------------------------
__global__ void __launch_bounds__(128, 4) attn_f(
    const uint32_t* __restrict__ qf, const uint32_t* __restrict__ kf,
    const uint32_t* __restrict__ vf, uint32_t* __restrict__ af)
{
    extern __shared__ __align__(16) uint32_t sm[];
    const uint32_t sb = smem_u32(sm);

    const int qt = gridDim.x - 1 - blockIdx.x;      // 0..31, longest-first
    const int bh = blockIdx.y;
    const int tid = threadIdx.x, warp = tid >> 5, lane = tid & 31;
    const int g = lane >> 2, t = lane & 3;

    auto issue_kv = [&](int it, int st) {
        uint32_t dK = sb + (2048u + (uint32_t)st * 4096u) * 4u;
        uint32_t dV = dK + 2048 * 4;
        const uint32_t* sK = kf + ((size_t)bh * 32 + it) * 2048;
        const uint32_t* sV = vf + ((size_t)bh * 32 + it) * 2048;
        #pragma unroll
        for (int i = 0; i < 4; i++) { int c = tid + 128 * i; CP16(dK + c*16, sK + c*4); }
        #pragma unroll
        for (int i = 0; i < 4; i++) { int c = tid + 128 * i; CP16(dV + c*16, sV + c*4); }
    };

    {   // prologue: Q, kv0, kv1 (three groups)
        const uint32_t* sQ = qf + ((size_t)bh * 32 + qt) * 2048;
        #pragma unroll
        for (int i = 0; i < 4; i++) { int c = tid + 128 * i; CP16(sb + c*16, sQ + c*4); }
        CPC();
        issue_kv(0, 0); CPC();
        if (qt >= 1) issue_kv(1, 1);
        CPC();
    }
    CPW(2);                 // Q arrived
    __syncthreads();

    // hoist Q fragments: warp w -> mtile w
    uint32_t aq[4][4];
    #pragma unroll
    for (int ks = 0; ks < 4; ks++) {
        int sl = (t ^ (g >> 1) ^ ks) & 3;
        uint4 av = *(const uint4*)&sm[ks*512 + warp*128 + g*16 + sl*4];
        aq[ks][0] = av.x; aq[ks][1] = av.y; aq[ks][2] = av.z; aq[ks][3] = av.w;
    }

    float o[8][4] = {};
    float csum[4] = {};
    const uint32_t bones[2] = {0x3C003C00u, 0x3C003C00u};   // ones fp16x2

    for (int it = 0; it <= qt; it++) {
        CPW(1);             // kv(it) ready; kv(it+1) may remain in flight
        __syncthreads();
        if (it + 2 <= qt) issue_kv(it + 2, (it + 2) % 3);
        CPC();
        const uint32_t* Kf = sm + 2048 + (it % 3) * 4096;
        const uint32_t* Vf = Kf + 2048;

        float s[8][4];
        #pragma unroll
        for (int nt = 0; nt < 8; nt++) { s[nt][0]=0.f; s[nt][1]=0.f; s[nt][2]=0.f; s[nt][3]=0.f; }

        // ---- S half A: n-tiles 0..3 (ntp 0,1) ----
        #pragma unroll
        for (int ks = 0; ks < 4; ks++) {
            int sl = (t ^ (g >> 1) ^ ks) & 3;
            #pragma unroll
            for (int ntp = 0; ntp < 2; ntp++) {
                uint4 kv4 = *(const uint4*)&Kf[ks*512 + ntp*128 + g*16 + sl*4];
                uint32_t blo[2] = {kv4.x, kv4.y};
                uint32_t bhi[2] = {kv4.z, kv4.w};
                mma16(s[2*ntp],     aq[ks], blo);
                mma16(s[2*ntp + 1], aq[ks], bhi);
            }
        }
        // ---- S half B: n-tiles 4..7 (ntp 2,3) ----
        #pragma unroll
        for (int ks = 0; ks < 4; ks++) {
            int sl = (t ^ (g >> 1) ^ ks) & 3;
            #pragma unroll
            for (int ntp = 2; ntp < 4; ntp++) {
                uint4 kv4 = *(const uint4*)&Kf[ks*512 + ntp*128 + g*16 + sl*4];
                uint32_t blo[2] = {kv4.x, kv4.y};
                uint32_t bhi[2] = {kv4.z, kv4.w};
                mma16(s[2*ntp],     aq[ks], blo);
                mma16(s[2*ntp + 1], aq[ks], bhi);
            }
        }

        // ---- ex2 half A -> A-frags ----
        uint32_t aA[2][4];
        #pragma unroll
        for (int kp = 0; kp < 2; kp++) {
            aA[kp][0] = ex2h2(f2h2(s[2*kp][0],   s[2*kp][1]));
            aA[kp][1] = ex2h2(f2h2(s[2*kp][2],   s[2*kp][3]));
            aA[kp][2] = ex2h2(f2h2(s[2*kp+1][0], s[2*kp+1][1]));
            aA[kp][3] = ex2h2(f2h2(s[2*kp+1][2], s[2*kp+1][3]));
        }
        // ---- PV half A ----
        #pragma unroll
        for (int kp = 0; kp < 2; kp++) {
            mma16(csum, aA[kp], bones);
            int sl = (t ^ (g >> 1) ^ kp) & 3;
            #pragma unroll
            for (int dtp = 0; dtp < 4; dtp++) {
                uint4 v4 = *(const uint4*)&Vf[kp*512 + dtp*128 + g*16 + sl*4];
                uint32_t blo[2] = {v4.x, v4.y};
                uint32_t bhi[2] = {v4.z, v4.w};
                mma16(o[2*dtp],     aA[kp], blo);
                mma16(o[2*dtp + 1], aA[kp], bhi);
            }
        }
        // ---- ex2 half B ----
        uint32_t aB[2][4];
        #pragma unroll
        for (int kp = 0; kp < 2; kp++) {
            int nt = 2 * (kp + 2);
            aB[kp][0] = ex2h2(f2h2(s[nt][0],   s[nt][1]));
            aB[kp][1] = ex2h2(f2h2(s[nt][2],   s[nt][3]));
            aB[kp][2] = ex2h2(f2h2(s[nt+1][0], s[nt+1][1]));
            aB[kp][3] = ex2h2(f2h2(s[nt+1][2], s[nt+1][3]));
        }
        // ---- PV half B ----
        #pragma unroll
        for (int kp = 0; kp < 2; kp++) {
            int ks = kp + 2;
            mma16(csum, aB[kp], bones);
            int sl = (t ^ (g >> 1) ^ ks) & 3;
            #pragma unroll
            for (int dtp = 0; dtp < 4; dtp++) {
                uint4 v4 = *(const uint4*)&Vf[ks*512 + dtp*128 + g*16 + sl*4];
                uint32_t blo[2] = {v4.x, v4.y};
                uint32_t bhi[2] = {v4.z, v4.w};
                mma16(o[2*dtp],     aB[kp], blo);
                mma16(o[2*dtp + 1], aB[kp], bhi);
            }
        }
    }

    // ---- epilogue: normalize, pack into proj-GEMM A-frag layout ----
    const int b_ = bh >> 4, h_ = bh & 15;
    float inv0 = 1.0f / csum[0];
    float inv1 = 1.0f / csum[2];
    #pragma unroll
    for (int dt = 0; dt < 8; dt++) {
        int pp = 4 * dt + t;                       // head-local pair index
        #pragma unroll
        for (int hm = 0; hm < 2; hm++) {
            int tok = qt * 64 + warp * 16 + g + hm * 8;
            float va = o[dt][2*hm + 0] * (hm ? inv1 : inv0);
            float vb = o[dt][2*hm + 1] * (hm ? inv1 : inv0);
            int m_out = b_ * TT + tok;
            int mb = m_out >> 7, row = m_out & 127;
            af[((size_t)mb * 16 + h_) * 4096 + a_off(row, pp)] = f2h2(va, vb);
        }
    }
}

// ---------------------------------------------------------------------------
extern "C" void kernel_launch(void* const* d_in, const int* in_sizes, int n_in,
                              void* d_out, int out_size)
{
    const float* x  = (const float*)d_in[0];
    const float* Wq = (const float*)d_in[1];
    const float* bq = (const float*)d_in[2];
    const float* Wk = (const float*)d_in[3];
    const float* bk = (const float*)d_in[4];
    const float* Wv = (const float*)d_in[5];
    const float* bv = (const float*)d_in[6];
    const float* Wp = (const float*)d_in[7];
    const float* bp = (const float*)d_in[8];

    float* yout = (float*)d_out;
    float* kout = yout + (size_t)BB * TT * CC;
    float* vout = kout + (size_t)BB * HH * TT * DD;

    uint32_t *xf, *wqf, *wkf, *wvf, *wpf, *qf, *kfr, *vfr, *afr;
    cudaGetSymbolAddress((void**)&xf,  g_xf);
    cudaGetSymbolAddress((void**)&wqf, g_wqf);
    cudaGetSymbolAddress((void**)&wkf, g_wkf);
    cudaGetSymbolAddress((void**)&wvf, g_wvf);
    cudaGetSymbolAddress((void**)&wpf, g_wpf);
    cudaGetSymbolAddress((void**)&qf,  g_qf);
    cudaGetSymbolAddress((void**)&kfr, g_kf);
    cudaGetSymbolAddress((void**)&vfr, g_vf);
    cudaGetSymbolAddress((void**)&afr, g_af);

    const int gsmem = GST * 8704 * 4;          // 104448 B
    const int asmem = (2048 + 3 * 4096) * 4;   // 57344 B
    cudaFuncSetAttribute(gemm_qkv,  cudaFuncAttributeMaxDynamicSharedMemorySize, gsmem);
    cudaFuncSetAttribute(gemm_proj, cudaFuncAttributeMaxDynamicSharedMemorySize, gsmem);
    cudaFuncSetAttribute(attn_f,    cudaFuncAttributeMaxDynamicSharedMemorySize, asmem);

    prep_all<<<dim3(1024, 8), 256>>>(x, Wq, Wk, Wv, Wp, xf, wqf, wkf, wvf, wpf);

    gemm_qkv<<<dim3(MM / 128, CC / 128, 3), 256, gsmem>>>(
        xf, wqf, wkf, wvf, bq, bk, bv, kout, vout, qf, kfr, vfr);

    attn_f<<<dim3(TT / 64, BB * HH), 128, asmem>>>(qf, kfr, vfr, afr);

    gemm_proj<<<dim3(MM / 128, CC / 128), 256, gsmem>>>(afr, wpf, bp, yout);
}